// round 17
// baseline (speedup 1.0000x reference)
#include <cuda_runtime.h>
#include <math.h>

// Problem shapes (fixed by dataset)
#define SS 2048
#define BB 32
#define HH 1024

// u GEMM tiling (proven R11/R12 config)
#define NOB 64
#define OC  16

#define GRID 148          // persistent co-resident blocks
#define NSTATIC 10        // static tasks per block (covers s < 1480)
#define SBASE (NSTATIC * GRID)   // 1480; tasks [1480, 2048) are stolen

// Scratch (static __device__ — no allocations allowed)
__device__ float g_u_part[NOB][BB * HH];  // 8 MB (L2-resident)
__device__ float g_u[BB * HH];            // 128 KB
__device__ float g_scores[BB * SS];       // 256 KB
__device__ unsigned g_sync[3];            // [0]=bar R, [1]=bar S, [2]=steal ctr

// ---------------------------------------------------------------------------
// K_A: u_part (proven body). grid (4, NOB, 2) = 512 x 256.
// ---------------------------------------------------------------------------
__global__ void k_upart(const float* __restrict__ hidden,
                        const float* __restrict__ W) {
    __shared__ float hs[OC * 16];
    const int t = threadIdx.x;
    const int h = blockIdx.x * 256 + t;
    const int o0 = blockIdx.y * OC;
    const int bbase = blockIdx.z * 16;

    if (t < OC * 16) {
        int o = t >> 4, bl = t & 15;
        hs[t] = hidden[(bbase + bl) * HH + o0 + o];
    }
    __syncthreads();

    float w[OC];
#pragma unroll
    for (int o = 0; o < OC; ++o)
        w[o] = W[(size_t)(o0 + o) * HH + h];

    float acc[16];
#pragma unroll
    for (int bl = 0; bl < 16; ++bl) acc[bl] = 0.f;

    const float4* hs4 = reinterpret_cast<const float4*>(hs);
#pragma unroll
    for (int o = 0; o < OC; ++o) {
#pragma unroll
        for (int q = 0; q < 4; ++q) {
            float4 hv = hs4[o * 4 + q];
            acc[q * 4 + 0] = fmaf(hv.x, w[o], acc[q * 4 + 0]);
            acc[q * 4 + 1] = fmaf(hv.y, w[o], acc[q * 4 + 1]);
            acc[q * 4 + 2] = fmaf(hv.z, w[o], acc[q * 4 + 2]);
            acc[q * 4 + 3] = fmaf(hv.w, w[o], acc[q * 4 + 3]);
        }
    }

#pragma unroll
    for (int bl = 0; bl < 16; ++bl)
        g_u_part[blockIdx.y][(bbase + bl) * HH + h] = acc[bl];
}

// ---------------------------------------------------------------------------
// Grid barrier among GRID co-resident blocks.
// ---------------------------------------------------------------------------
__device__ __forceinline__ void grid_barrier(int id) {
    __syncthreads();
    if (threadIdx.x == 0) {
        __threadfence();                       // release
        atomicAdd(&g_sync[id], 1u);
        while (atomicAdd(&g_sync[id], 0u) < GRID) __nanosleep(32);
        __threadfence();                       // acquire
    }
    __syncthreads();
}

// ---------------------------------------------------------------------------
// K_C: ureduce (fused, R14-proven) + scores (static 10 + work-steal tail)
//      + softmax. One kernel, 148 x 1024.
// Scores stream is at its pattern ceiling (~5.4-5.6 TB/s with BOTH register
// LDG and smem bulk-async pipelines -> chip floor, not SM-limited). The
// remaining losses are the launch gap (fused away here) and the per-block
// finish-time spread (L2-die variance, ~10% over a 47us phase) — absorbed
// by stealing the last 568 tasks at one atomic each.
// ---------------------------------------------------------------------------
__global__ void __launch_bounds__(1024, 1)
k_main(const float* __restrict__ enc, float* __restrict__ out) {
    const int t = threadIdx.x;
    const int warp = t >> 5;
    const int lane = t & 31;
    const int b = warp;
    const int blk = blockIdx.x;

    __shared__ float red[32];
    __shared__ int ds;

    // ---- Phase R: reduce 64 partials, contiguous coalesced ranges ----
    {
        int ofs, cnt;
        if (blk < 60) { ofs = blk * 222; cnt = 222; }
        else          { ofs = 60 * 222 + (blk - 60) * 221; cnt = 221; }
        if (t < cnt) {
            const int i = ofs + t;
            float s = 0.f;
#pragma unroll 8
            for (int p = 0; p < NOB; ++p) s += g_u_part[p][i];
            g_u[i] = s;
        }
    }
    grid_barrier(0);

    // u[b] -> registers, once per block
    const float4* ub = reinterpret_cast<const float4*>(g_u + b * HH);
    float4 u[8];
#pragma unroll
    for (int c = 0; c < 8; ++c) u[c] = ub[c * 32 + lane];

    // ---- Phase S1: static interleaved tasks (sync-free, proven loop) ----
#pragma unroll 1
    for (int k = 0; k < NSTATIC; ++k) {
        const int s = blk + k * GRID;        // s < 1480
        const float4* r =
            reinterpret_cast<const float4*>(enc + ((size_t)s * BB + b) * HH);
        float a = 0.f;
#pragma unroll
        for (int c = 0; c < 8; ++c) {
            float4 e = __ldcs(&r[c * 32 + lane]);
            a += e.x * u[c].x + e.y * u[c].y + e.z * u[c].z + e.w * u[c].w;
        }
#pragma unroll
        for (int off = 16; off; off >>= 1)
            a += __shfl_xor_sync(0xFFFFFFFFu, a, off);
        if (lane == 0) g_scores[b * SS + s] = a;
    }

    // ---- Phase S2: work-steal tail (tasks 1480..2047) ----
    for (;;) {
        if (t == 0) ds = SBASE + (int)atomicAdd(&g_sync[2], 1u);
        __syncthreads();
        const int s = ds;
        __syncthreads();
        if (s >= SS) break;

        const float4* r =
            reinterpret_cast<const float4*>(enc + ((size_t)s * BB + b) * HH);
        float a = 0.f;
#pragma unroll
        for (int c = 0; c < 8; ++c) {
            float4 e = __ldcs(&r[c * 32 + lane]);
            a += e.x * u[c].x + e.y * u[c].y + e.z * u[c].z + e.w * u[c].w;
        }
#pragma unroll
        for (int off = 16; off; off >>= 1)
            a += __shfl_xor_sync(0xFFFFFFFFu, a, off);
        if (lane == 0) g_scores[b * SS + s] = a;
    }
    grid_barrier(1);

    // ---- Phase M: softmax (blocks 0..31, batch bb = blk) ----
    if (blk < BB) {
        const int bb = blk;
        float v0 = g_scores[bb * SS + t];
        float v1 = g_scores[bb * SS + t + 1024];

        float m = fmaxf(v0, v1);
#pragma unroll
        for (int off = 16; off; off >>= 1)
            m = fmaxf(m, __shfl_xor_sync(0xFFFFFFFFu, m, off));
        if (lane == 0) red[warp] = m;
        __syncthreads();
        if (warp == 0) {
            float x = red[lane];
#pragma unroll
            for (int off = 16; off; off >>= 1)
                x = fmaxf(x, __shfl_xor_sync(0xFFFFFFFFu, x, off));
            if (lane == 0) red[0] = x;
        }
        __syncthreads();
        const float bm = red[0];
        __syncthreads();  // before reusing red[]

        v0 = __expf(v0 - bm);
        v1 = __expf(v1 - bm);
        float s = v0 + v1;
#pragma unroll
        for (int off = 16; off; off >>= 1)
            s += __shfl_xor_sync(0xFFFFFFFFu, s, off);
        if (lane == 0) red[warp] = s;
        __syncthreads();
        if (warp == 0) {
            float x = red[lane];
#pragma unroll
            for (int off = 16; off; off >>= 1)
                x += __shfl_xor_sync(0xFFFFFFFFu, x, off);
            if (lane == 0) red[0] = x;
        }
        __syncthreads();
        const float inv = 1.f / red[0];

        out[bb * SS + t]        = v0 * inv;
        out[bb * SS + t + 1024] = v1 * inv;
    }
}

// ---------------------------------------------------------------------------
// Inputs (metadata order): hidden [B,H], encoder_outputs [S,B,H], W [H,H], b [H]
// Bias is irrelevant (softmax shift invariance).
// ---------------------------------------------------------------------------
extern "C" void kernel_launch(void* const* d_in, const int* in_sizes, int n_in,
                              void* d_out, int out_size) {
    const float* hidden = (const float*)d_in[0];
    const float* enc    = (const float*)d_in[1];
    const float* W      = (const float*)d_in[2];
    float* out          = (float*)d_out;

    // Zero barriers + steal counter each invocation (captured graph node).
    void* sync_ptr;
    cudaGetSymbolAddress(&sync_ptr, g_sync);
    cudaMemsetAsync(sync_ptr, 0, sizeof(unsigned) * 3);

    k_upart<<<dim3(HH / 256, NOB, 2), 256>>>(hidden, W);
    k_main<<<GRID, 1024>>>(enc, out);
}